// round 3
// baseline (speedup 1.0000x reference)
#include <cuda_runtime.h>
#include <cstdint>

#define B_    128
#define S_    1024
#define EMB_  100
#define EDIM_ 256
#define H_    1024

// Scratch (device globals: allocation-free rule)
__device__ float       g_I[S_ * B_ * H_];      // [s*128+b][h]  512 MB
__device__ signed char g_Xq[S_ * B_ * EDIM_];  // quantized layer-1 acts *16
__device__ signed char g_W2q[H_ * EDIM_];      // round(W2*16)
__device__ signed char g_Wrq[H_ * H_];         // round(Wr2*16)
__device__ float       g_sum[B_ * H_];         // spike counts

__device__ __forceinline__ uint32_t smem_u32(const void* p) {
    uint32_t a;
    asm("{ .reg .u64 t; cvta.to.shared.u64 t, %1; cvt.u32.u64 %0, t; }" : "=r"(a) : "l"(p));
    return a;
}

// ---------------- K0: weight quantization --------------------------------
__global__ void k_quant(const float* __restrict__ W2, const float* __restrict__ Wr2) {
    int i = blockIdx.x * blockDim.x + threadIdx.x;
    if (i < H_ * EDIM_) {
        float v = rintf(W2[i] * 16.f);
        v = fminf(fmaxf(v, -15.f), 15.f);
        g_W2q[i] = (signed char)v;
    }
    if (i < H_ * H_) {
        float v = rintf(Wr2[i] * 16.f);
        v = fminf(fmaxf(v, -15.f), 15.f);
        g_Wrq[i] = (signed char)v;
    }
}

// ---------------- K1: embedding + layer1 + quant_act ----------------------
__global__ __launch_bounds__(256) void k_embed_l1(
    const int* __restrict__ inputs, const float* __restrict__ emb,
    const float* __restrict__ W1, const float* __restrict__ b1)
{
    extern __shared__ char sm[];
    float* w1t = (float*)sm;               // [100][257]
    float* xs  = (float*)(sm + 102912);    // [64][104]
    float* b1s = (float*)(sm + 129536);
    int*   tok = (int*)(sm + 130560);

    int t = threadIdx.x;
    for (int idx = t; idx < EDIM_ * EMB_; idx += 256) {
        int h = idx / EMB_;
        int e = idx - h * EMB_;
        w1t[e * 257 + h] = W1[idx];
    }
    b1s[t] = b1[t];
    int r0 = blockIdx.x * 64;
    if (t < 64) {
        int R = r0 + t;
        tok[t] = inputs[(R & 127) * S_ + (R >> 7)];
    }
    __syncthreads();
    for (int idx = t; idx < 64 * 104; idx += 256) {
        int r = idx / 104;
        int e = idx - r * 104;
        xs[idx] = (e < EMB_) ? emb[tok[r] * EMB_ + e] : 0.f;
    }
    __syncthreads();

    int h = t;
    for (int rb = 0; rb < 8; rb++) {
        float acc[8];
#pragma unroll
        for (int i = 0; i < 8; i++) acc[i] = 0.f;
        for (int ec = 0; ec < 25; ec++) {
            float w0 = w1t[(4 * ec + 0) * 257 + h];
            float w1v = w1t[(4 * ec + 1) * 257 + h];
            float w2v = w1t[(4 * ec + 2) * 257 + h];
            float w3v = w1t[(4 * ec + 3) * 257 + h];
#pragma unroll
            for (int r8 = 0; r8 < 8; r8++) {
                const float4 x4 = *(const float4*)(xs + (rb * 8 + r8) * 104 + 4 * ec);
                acc[r8] += x4.x * w0 + x4.y * w1v + x4.z * w2v + x4.w * w3v;
            }
        }
#pragma unroll
        for (int r8 = 0; r8 < 8; r8++) {
            int R = r0 + rb * 8 + r8;
            float v = acc[r8] + b1s[h];
            v = fmaxf(v, 0.f);
            float q = fminf(rintf(v * 16.f), 15.f);
            g_Xq[R * EDIM_ + h] = (signed char)q;
        }
    }
}

// ---------------- K2: I = Xq @ W2q^T / 256 (dp4a GEMM) ---------------------
__global__ __launch_bounds__(256, 2) void k_gemm_I() {
    extern __shared__ char sm[];
    int* xsm = (int*)sm;              // [128][64]
    int* wsm = (int*)(sm + 32768);    // [64][129]
    int t = threadIdx.x;
    int rt0 = blockIdx.y * 128;
    int ht0 = blockIdx.x * 128;
    const int* Xw = (const int*)g_Xq;
    const int* Ww = (const int*)g_W2q;
    for (int idx = t; idx < 8192; idx += 256) {
        int r = idx >> 6, kc = idx & 63;
        xsm[r * 64 + kc] = Xw[(rt0 + r) * 64 + kc];
        wsm[kc * 129 + r] = Ww[(ht0 + r) * 64 + kc];
    }
    __syncthreads();
    int tx = t & 15, ty = t >> 4;
    int acc[8][8];
#pragma unroll
    for (int i = 0; i < 8; i++)
#pragma unroll
        for (int j = 0; j < 8; j++) acc[i][j] = 0;

    for (int kc = 0; kc < 64; kc++) {
        int a[8], b[8];
#pragma unroll
        for (int i = 0; i < 8; i++) a[i] = xsm[(ty * 8 + i) * 64 + kc];
#pragma unroll
        for (int j = 0; j < 8; j++) b[j] = wsm[kc * 129 + tx + 16 * j];
#pragma unroll
        for (int i = 0; i < 8; i++)
#pragma unroll
            for (int j = 0; j < 8; j++) acc[i][j] = __dp4a(a[i], b[j], acc[i][j]);
    }
#pragma unroll
    for (int i = 0; i < 8; i++)
#pragma unroll
        for (int j = 0; j < 8; j++)
            g_I[(size_t)(rt0 + ty * 8 + i) * 1024 + ht0 + tx + 16 * j] =
                (float)acc[i][j] * (1.f / 256.f);
}

// ---------------- K3: recurrent LIF scan (v2) -------------------------------
// 16 clusters x 8 CTAs x 512 threads. thread = (h in [0,128), bq in {0,1}, kh in {0,1}).
// Each thread: 4 batches, half of K. Spike exchange: remote st.shared::cluster of
// packed words + fence.acq_rel.cluster + per-rank mbarrier arrive (double-buffered).
__global__ void __cluster_dims__(8, 1, 1) __launch_bounds__(512, 1)
k_scan(const float* __restrict__ b2, const float* __restrict__ br2)
{
    extern __shared__ char sm[];
    int4*     wrT  = (int4*)sm;                   // [64][129] int4 = 132096 B
    unsigned* spkb = (unsigned*)(sm + 132096);    // [8][256] words = 8192 B
    unsigned* pk   = (unsigned*)(sm + 140288);    // [2][8][32]     = 2048 B
    int*      red  = (int*)(sm + 142336);         // [8][128]       = 4096 B
    float*    b2s  = (float*)(sm + 146432);       // 512 B
    float*    brs  = (float*)(sm + 146944);       // 512 B
    // mbars at 147456: [2] x 8B

    int t = threadIdx.x;
    int cr = blockIdx.x & 7;                      // cluster rank
    int b0 = (blockIdx.x >> 3) * 8;               // batch base of this cluster
    int h0 = cr * 128;

    uint32_t smb     = smem_u32(sm);
    uint32_t pk_a    = smb + 140288;
    uint32_t mb_a    = smb + 147456;

    // ---- init ----
    const int4* Wr4 = (const int4*)g_Wrq;
    for (int idx = t; idx < 8192; idx += 512) {
        int hh = idx >> 6, c = idx & 63;
        wrT[c * 129 + hh] = Wr4[(h0 + hh) * 64 + c];
    }
    if (t < 128) { b2s[t] = b2[h0 + t]; brs[t] = br2[h0 + t]; }
    if (t < 512) pk[t] = 0u;
    if (t == 0) {
        asm volatile("mbarrier.init.shared.b64 [%0], 8;" :: "r"(mb_a) : "memory");
        asm volatile("mbarrier.init.shared.b64 [%0], 8;" :: "r"(mb_a + 8) : "memory");
    }
    __syncthreads();
    asm volatile("barrier.cluster.arrive.aligned;" ::: "memory");
    asm volatile("barrier.cluster.wait.aligned;" ::: "memory");

    int h    = t & 127;
    int bq   = (t >> 7) & 1;
    int kh   = t >> 8;
    int lane = t & 31;
    int warp = t >> 5;
    int hseg = h >> 5;
    int c0   = kh * 32;

    float mem[4], spf[4];
    int   cnt[4];
#pragma unroll
    for (int b = 0; b < 4; b++) { mem[b] = 0.f; spf[b] = 0.f; cnt[b] = 0; }

    unsigned ph[2] = {0u, 0u};
    const float* Ib = g_I + ((size_t)(b0 + bq * 4)) * 1024 + h0 + h;
    const int4* sp4 = (const int4*)spkb;

    for (int s = 0; s < 1024; s++) {
        int q = s & 1;
        // ---- wait for spike data (unpackers only; others sync at barrier) ----
        if (t < 256) {
            if (s > 0) {
                uint32_t addr = mb_a + q * 8;
                unsigned par = ph[q];
                ph[q] ^= 1u;
                unsigned done = 0;
                while (!done) {
                    asm volatile(
                        "{\n\t.reg .pred p;\n\t"
                        "mbarrier.try_wait.parity.acquire.cluster.shared::cta.b64 p, [%1], %2;\n\t"
                        "selp.b32 %0, 1, 0, p;\n\t}"
                        : "=r"(done) : "r"(addr), "r"(par) : "memory");
                }
            } else {
                ph[q] ^= 0u;
            }
            // unpack bits -> 0/1 bytes
            unsigned w = pk[q * 256 + t];
            int bb = t >> 5, wi = t & 31;
#pragma unroll
            for (int k = 0; k < 8; k++) {
                unsigned u = (w >> (4 * k)) & 0xFu;
                unsigned word = (u & 1u) | ((u << 7) & 0x100u) |
                                ((u << 14) & 0x10000u) | ((u << 21) & 0x1000000u);
                spkb[bb * 256 + wi * 8 + k] = word;
            }
        } else if (s > 0) {
            ph[q] ^= 1u;  // keep counters consistent (unused by kh1)
        }
        __syncthreads();

        // ---- feed-forward currents (exact, precomputed) ----
        float Iv[4];
        if (kh == 0) {
#pragma unroll
            for (int b = 0; b < 4; b++) Iv[b] = Ib[(size_t)b * 1024];
        }

        // ---- half-K dp4a GEMV ----
        int acc[4] = {0, 0, 0, 0};
        const int4* wp = wrT + c0 * 129 + h;
        const int4* sb = sp4 + bq * 256 + c0;
#pragma unroll 4
        for (int c = 0; c < 32; c++) {
            int4 w = wp[c * 129];
#pragma unroll
            for (int b = 0; b < 4; b++) {
                int4 sv = sb[b * 64 + c];
                acc[b] = __dp4a(w.x, sv.x, acc[b]);
                acc[b] = __dp4a(w.y, sv.y, acc[b]);
                acc[b] = __dp4a(w.z, sv.z, acc[b]);
                acc[b] = __dp4a(w.w, sv.w, acc[b]);
            }
        }
        if (kh == 1) {
#pragma unroll
            for (int b = 0; b < 4; b++) red[(bq * 4 + b) * 128 + h] = acc[b];
        }
        __syncthreads();

        if (kh == 0) {
            unsigned bal[4];
#pragma unroll
            for (int b = 0; b < 4; b++) {
                int a = acc[b] + red[(bq * 4 + b) * 128 + h];
                float R = (float)a * 0.0625f;                 // exact
                float m = __fmul_rn(mem[b], 0.2f);
                if (spf[b] != 0.f) m = 0.f;                   // *(1-spike)
                m = __fadd_rn(m, Iv[b]);
                m = __fadd_rn(m, b2s[h]);
                m = __fadd_rn(m, R);
                m = __fadd_rn(m, brs[h]);
                mem[b] = m;
                bool sk = m > 0.5f;
                spf[b] = sk ? 1.f : 0.f;
                cnt[b] += sk ? 1 : 0;
                bal[b] = __ballot_sync(0xffffffffu, sk);
            }
            // export: lane l -> batch (l&3), rank (l>>2); one remote word store
            int bloc = lane & 3;
            int rank = lane >> 2;
            unsigned word = (bloc == 0) ? bal[0] : (bloc == 1) ? bal[1]
                          : (bloc == 2) ? bal[2] : bal[3];
            int qn = (s + 1) & 1;
            uint32_t dst = pk_a + (uint32_t)(qn * 256 + (bq * 4 + bloc) * 32 + cr * 4 + hseg) * 4u;
            asm volatile(
                "{\n\t.reg .b32 ra;\n\t"
                "mapa.shared::cluster.u32 ra, %0, %1;\n\t"
                "st.shared::cluster.b32 [ra], %2;\n\t}"
                :: "r"(dst), "r"(rank), "r"(word) : "memory");

            // all storing warps (0-7) rendezvous, then warp 0 publishes
            asm volatile("bar.sync 1, 256;" ::: "memory");
            if (warp == 0) {
                asm volatile("fence.acq_rel.cluster;" ::: "memory");
                if (lane < 8) {
                    uint32_t mloc = mb_a + (uint32_t)qn * 8u;
                    asm volatile(
                        "{\n\t.reg .b32 ra;\n\t"
                        "mapa.shared::cluster.u32 ra, %0, %1;\n\t"
                        "mbarrier.arrive.release.cluster.shared::cluster.b64 _, [ra];\n\t}"
                        :: "r"(mloc), "r"(lane) : "memory");
                }
            }
        }
        Ib += 131072;   // next step
    }

    if (kh == 0) {
#pragma unroll
        for (int b = 0; b < 4; b++)
            g_sum[(b0 + bq * 4 + b) * 1024 + h0 + h] = (float)cnt[b];
    }
    asm volatile("barrier.cluster.arrive.aligned;" ::: "memory");
    asm volatile("barrier.cluster.wait.aligned;" ::: "memory");
}

// ---------------- K4: readout ---------------------------------------------
__global__ void k_out(const float* __restrict__ W3, const float* __restrict__ b3,
                      float* __restrict__ out)
{
    __shared__ float s0[128], s1[128];
    int b = blockIdx.x, t = threadIdx.x;
    float a0 = 0.f, a1 = 0.f;
    for (int hh = t; hh < 1024; hh += 128) {
        float s = g_sum[b * 1024 + hh];
        a0 += s * W3[hh];
        a1 += s * W3[1024 + hh];
    }
    s0[t] = a0; s1[t] = a1;
    __syncthreads();
    for (int o = 64; o > 0; o >>= 1) {
        if (t < o) { s0[t] += s0[t + o]; s1[t] += s1[t + o]; }
        __syncthreads();
    }
    if (t == 0) {
        out[b * 2 + 0] = s0[0] + b3[0];
        out[b * 2 + 1] = s1[0] + b3[1];
    }
}

// ---------------- launch ----------------------------------------------------
extern "C" void kernel_launch(void* const* d_in, const int* in_sizes, int n_in,
                              void* d_out, int out_size)
{
    const int*   inputs = (const int*)d_in[0];
    const float* emb    = (const float*)d_in[1];
    const float* W1     = (const float*)d_in[2];
    const float* b1     = (const float*)d_in[3];
    const float* W2     = (const float*)d_in[4];
    const float* b2     = (const float*)d_in[5];
    const float* Wr2    = (const float*)d_in[6];
    const float* br2    = (const float*)d_in[7];
    const float* W3     = (const float*)d_in[8];
    const float* b3     = (const float*)d_in[9];
    float* out = (float*)d_out;

    cudaFuncSetAttribute(k_embed_l1, cudaFuncAttributeMaxDynamicSharedMemorySize, 131072);
    cudaFuncSetAttribute(k_gemm_I,  cudaFuncAttributeMaxDynamicSharedMemorySize, 66560);
    cudaFuncSetAttribute(k_scan,    cudaFuncAttributeMaxDynamicSharedMemorySize, 147472);

    k_quant<<<(H_ * H_ + 255) / 256, 256>>>(W2, Wr2);
    k_embed_l1<<<2048, 256, 130816>>>(inputs, emb, W1, b1);
    k_gemm_I<<<dim3(8, 1024), 256, 65792>>>();
    k_scan<<<128, 512, 147472>>>(b2, br2);
    k_out<<<128, 128>>>(W3, b3, out);
}

// round 4
// speedup vs baseline: 1.3840x; 1.3840x over previous
#include <cuda_runtime.h>
#include <cstdint>

#define B_    128
#define S_    1024
#define EMB_  100
#define EDIM_ 256
#define H_    1024

// Scratch (device globals: allocation-free rule)
__device__ float       g_I[S_ * B_ * H_];      // [s*128+b][h]  512 MB
__device__ signed char g_Xq[S_ * B_ * EDIM_];  // quantized layer-1 acts *16
__device__ signed char g_W2q[H_ * EDIM_];      // round(W2*16)
__device__ signed char g_Wrq[H_ * H_];         // round(Wr2*16)
__device__ float       g_sum[B_ * H_];         // spike counts

__device__ __forceinline__ uint32_t smem_u32(const void* p) {
    uint32_t a;
    asm("{ .reg .u64 t; cvta.to.shared.u64 t, %1; cvt.u32.u64 %0, t; }" : "=r"(a) : "l"(p));
    return a;
}

// ---------------- K0: weight quantization --------------------------------
__global__ void k_quant(const float* __restrict__ W2, const float* __restrict__ Wr2) {
    int i = blockIdx.x * blockDim.x + threadIdx.x;
    if (i < H_ * EDIM_) {
        float v = rintf(W2[i] * 16.f);
        v = fminf(fmaxf(v, -15.f), 15.f);
        g_W2q[i] = (signed char)v;
    }
    if (i < H_ * H_) {
        float v = rintf(Wr2[i] * 16.f);
        v = fminf(fmaxf(v, -15.f), 15.f);
        g_Wrq[i] = (signed char)v;
    }
}

// ---------------- K1: embedding + layer1 + quant_act ----------------------
__global__ __launch_bounds__(256) void k_embed_l1(
    const int* __restrict__ inputs, const float* __restrict__ emb,
    const float* __restrict__ W1, const float* __restrict__ b1)
{
    extern __shared__ char sm[];
    float* w1t = (float*)sm;               // [100][257]
    float* xs  = (float*)(sm + 102912);    // [64][104]
    float* b1s = (float*)(sm + 129536);
    int*   tok = (int*)(sm + 130560);

    int t = threadIdx.x;
    for (int idx = t; idx < EDIM_ * EMB_; idx += 256) {
        int h = idx / EMB_;
        int e = idx - h * EMB_;
        w1t[e * 257 + h] = W1[idx];
    }
    b1s[t] = b1[t];
    int r0 = blockIdx.x * 64;
    if (t < 64) {
        int R = r0 + t;
        tok[t] = inputs[(R & 127) * S_ + (R >> 7)];
    }
    __syncthreads();
    for (int idx = t; idx < 64 * 104; idx += 256) {
        int r = idx / 104;
        int e = idx - r * 104;
        xs[idx] = (e < EMB_) ? emb[tok[r] * EMB_ + e] : 0.f;
    }
    __syncthreads();

    int h = t;
    for (int rb = 0; rb < 8; rb++) {
        float acc[8];
#pragma unroll
        for (int i = 0; i < 8; i++) acc[i] = 0.f;
        for (int ec = 0; ec < 25; ec++) {
            float w0 = w1t[(4 * ec + 0) * 257 + h];
            float w1v = w1t[(4 * ec + 1) * 257 + h];
            float w2v = w1t[(4 * ec + 2) * 257 + h];
            float w3v = w1t[(4 * ec + 3) * 257 + h];
#pragma unroll
            for (int r8 = 0; r8 < 8; r8++) {
                const float4 x4 = *(const float4*)(xs + (rb * 8 + r8) * 104 + 4 * ec);
                acc[r8] += x4.x * w0 + x4.y * w1v + x4.z * w2v + x4.w * w3v;
            }
        }
#pragma unroll
        for (int r8 = 0; r8 < 8; r8++) {
            int R = r0 + rb * 8 + r8;
            float v = acc[r8] + b1s[h];
            v = fmaxf(v, 0.f);
            float q = fminf(rintf(v * 16.f), 15.f);
            g_Xq[R * EDIM_ + h] = (signed char)q;
        }
    }
}

// ---------------- K2: I = Xq @ W2q^T / 256 (dp4a GEMM) ---------------------
__global__ __launch_bounds__(256, 2) void k_gemm_I() {
    extern __shared__ char sm[];
    int* xsm = (int*)sm;              // [128][64]
    int* wsm = (int*)(sm + 32768);    // [64][129]
    int t = threadIdx.x;
    int rt0 = blockIdx.y * 128;
    int ht0 = blockIdx.x * 128;
    const int* Xw = (const int*)g_Xq;
    const int* Ww = (const int*)g_W2q;
    for (int idx = t; idx < 8192; idx += 256) {
        int r = idx >> 6, kc = idx & 63;
        xsm[r * 64 + kc] = Xw[(rt0 + r) * 64 + kc];
        wsm[kc * 129 + r] = Ww[(ht0 + r) * 64 + kc];
    }
    __syncthreads();
    int tx = t & 15, ty = t >> 4;
    int acc[8][8];
#pragma unroll
    for (int i = 0; i < 8; i++)
#pragma unroll
        for (int j = 0; j < 8; j++) acc[i][j] = 0;

    for (int kc = 0; kc < 64; kc++) {
        int a[8], b[8];
#pragma unroll
        for (int i = 0; i < 8; i++) a[i] = xsm[(ty * 8 + i) * 64 + kc];
#pragma unroll
        for (int j = 0; j < 8; j++) b[j] = wsm[kc * 129 + tx + 16 * j];
#pragma unroll
        for (int i = 0; i < 8; i++)
#pragma unroll
            for (int j = 0; j < 8; j++) acc[i][j] = __dp4a(a[i], b[j], acc[i][j]);
    }
#pragma unroll
    for (int i = 0; i < 8; i++)
#pragma unroll
        for (int j = 0; j < 8; j++)
            g_I[(size_t)(rt0 + ty * 8 + i) * 1024 + ht0 + tx + 16 * j] =
                (float)acc[i][j] * (1.f / 256.f);
}

// ---------------- K3: recurrent LIF scan (v3: tensor-core IMMA) -------------
// 16 clusters x 8 CTAs x 256 threads. CTA = 128 h-rows x 8 batches.
// Warp w owns h rows [16w, 16w+16). Per step, per warp: 32 x
// (ldmatrix.x4 A from swizzled SMEM weights + B-frag built from packed spike
// bits + mma.sync.m16n8k32.s8). Spike exchange: packed bits, double-buffered,
// remote st.shared::cluster + cluster.sync (v1-proven protocol).
__global__ void __cluster_dims__(8, 1, 1) __launch_bounds__(256, 1)
k_scan(const float* __restrict__ b2, const float* __restrict__ br2)
{
    extern __shared__ char sm[];
    // [0, 131072)        W slab, 128 rows x 1024 B, 16B-unit XOR swizzle
    // [131072, 133376)   pk[2][8][36] packed spike words (row stride 36)
    // [133376, 134400)   sb[8][128] spike byte staging
    unsigned*      pk = (unsigned*)(sm + 131072);
    unsigned char* sb = (unsigned char*)(sm + 133376);

    int t  = threadIdx.x;
    int cr = blockIdx.x & 7;            // cluster rank
    int b0 = (blockIdx.x >> 3) * 8;     // global batch base
    int h0 = cr * 128;                  // global h base

    uint32_t smb  = smem_u32(sm);
    uint32_t pk_a = smb + 131072;

    // ---- init: swizzled weight slab + zero pk ----
    const int4* Wr4 = (const int4*)g_Wrq;
    int4* wS4 = (int4*)sm;
    for (int idx = t; idx < 8192; idx += 256) {
        int hh = idx >> 6, u = idx & 63;
        wS4[hh * 64 + (u ^ (hh & 7))] = Wr4[(h0 + hh) * 64 + u];
    }
    for (int i = t; i < 576; i += 256) pk[i] = 0u;
    __syncthreads();
    asm volatile("barrier.cluster.arrive.aligned;" ::: "memory");
    asm volatile("barrier.cluster.wait.aligned;" ::: "memory");

    int lane = t & 31, w = t >> 5;
    int qd = lane >> 2;                 // l/4: C row, B batch
    int qm = lane & 3;                  // l%4
    int h_lo = 16 * w + qd;             // C rows: h_lo, h_lo+8
    int bl0  = qm * 2;                  // C cols: bl0, bl0+1

    // ldmatrix source lane mapping
    int mm  = lane >> 3, r8 = lane & 7;
    int lrow = 16 * w + ((mm & 1) << 3) + r8;
    int uhi  = mm >> 1;
    uint32_t arow = smb + (uint32_t)lrow * 1024u;
    int sbit = qm * 4;

    float b2lo = b2[h0 + h_lo], b2hi = b2[h0 + h_lo + 8];
    float brlo = br2[h0 + h_lo], brhi = br2[h0 + h_lo + 8];

    float mem[4] = {0.f, 0.f, 0.f, 0.f};
    float spf[4] = {0.f, 0.f, 0.f, 0.f};
    int   cnt[4] = {0, 0, 0, 0};

    const float* Ib = g_I + (size_t)b0 * 1024 + h0;

    for (int s = 0; s < 1024; s++) {
        int q = s & 1, qn = q ^ 1;

        // prefetch feed-forward currents (exact, precomputed)
        float Iv0 = Ib[(size_t)(bl0    ) * 1024 + h_lo];
        float Iv1 = Ib[(size_t)(bl0 + 1) * 1024 + h_lo];
        float Iv2 = Ib[(size_t)(bl0    ) * 1024 + h_lo + 8];
        float Iv3 = Ib[(size_t)(bl0 + 1) * 1024 + h_lo + 8];

        int c[16];
#pragma unroll
        for (int i = 0; i < 16; i++) c[i] = 0;

        const unsigned* pkq = pk + q * 288 + qd * 36;
#pragma unroll
        for (int kc = 0; kc < 32; kc++) {
            unsigned wbits = pkq[kc];
            unsigned u0 = (wbits >> sbit) & 0xFu;
            unsigned u1 = (wbits >> (sbit + 16)) & 0xFu;
            unsigned bb0 = (u0 * 0x204081u) & 0x01010101u;
            unsigned bb1 = (u1 * 0x204081u) & 0x01010101u;
            uint32_t addr = arow + (uint32_t)(((kc * 2 + uhi) ^ r8) << 4);
            unsigned a0, a1, a2, a3;
            asm volatile(
                "ldmatrix.sync.aligned.m8n8.x4.shared.b16 {%0,%1,%2,%3}, [%4];"
                : "=r"(a0), "=r"(a1), "=r"(a2), "=r"(a3) : "r"(addr));
            int* cc = c + (kc & 3) * 4;
            asm volatile(
                "mma.sync.aligned.m16n8k32.row.col.s32.s8.s8.s32 "
                "{%0,%1,%2,%3}, {%4,%5,%6,%7}, {%8,%9}, {%0,%1,%2,%3};"
                : "+r"(cc[0]), "+r"(cc[1]), "+r"(cc[2]), "+r"(cc[3])
                : "r"(a0), "r"(a1), "r"(a2), "r"(a3), "r"(bb0), "r"(bb1));
        }
        int acc0 = (c[0] + c[4])  + (c[8]  + c[12]);
        int acc1 = (c[1] + c[5])  + (c[9]  + c[13]);
        int acc2 = (c[2] + c[6])  + (c[10] + c[14]);
        int acc3 = (c[3] + c[7])  + (c[11] + c[15]);

        // membrane update (exact replication of reference op order)
        float Ivs[4] = {Iv0, Iv1, Iv2, Iv3};
        int   accs[4] = {acc0, acc1, acc2, acc3};
#pragma unroll
        for (int r = 0; r < 4; r++) {
            float R = (float)accs[r] * 0.0625f;               // exact
            float m = __fmul_rn(mem[r], 0.2f);
            if (spf[r] != 0.f) m = 0.f;                       // *(1-spike)
            m = __fadd_rn(m, Ivs[r]);
            m = __fadd_rn(m, (r >= 2) ? b2hi : b2lo);
            m = __fadd_rn(m, R);
            m = __fadd_rn(m, (r >= 2) ? brhi : brlo);
            mem[r] = m;
            bool sk = m > 0.5f;
            spf[r] = sk ? 1.f : 0.f;
            cnt[r] += sk ? 1 : 0;
            int hh = h_lo + ((r >= 2) ? 8 : 0);
            int bb = bl0 + (r & 1);
            sb[bb * 128 + hh] = sk ? 1u : 0u;
        }
        __syncthreads();

        // pack: warp w packs batch w (4 words of 32 h-bits), broadcast to 8 ranks
        unsigned bal0 = __ballot_sync(0xffffffffu, sb[w * 128 +  0 + lane] != 0);
        unsigned bal1 = __ballot_sync(0xffffffffu, sb[w * 128 + 32 + lane] != 0);
        unsigned bal2 = __ballot_sync(0xffffffffu, sb[w * 128 + 64 + lane] != 0);
        unsigned bal3 = __ballot_sync(0xffffffffu, sb[w * 128 + 96 + lane] != 0);
        {
            int rank = lane >> 2;
            int wi   = lane & 3;
            unsigned word = (wi == 0) ? bal0 : (wi == 1) ? bal1
                          : (wi == 2) ? bal2 : bal3;
            uint32_t dst = pk_a + (uint32_t)(qn * 288 + w * 36 + cr * 4 + wi) * 4u;
            asm volatile(
                "{\n\t.reg .b32 ra;\n\t"
                "mapa.shared::cluster.u32 ra, %0, %1;\n\t"
                "st.shared::cluster.b32 [ra], %2;\n\t}"
                :: "r"(dst), "r"(rank), "r"(word) : "memory");
        }
        asm volatile("barrier.cluster.arrive.aligned;" ::: "memory");
        asm volatile("barrier.cluster.wait.aligned;" ::: "memory");
        Ib += 131072;
    }

#pragma unroll
    for (int r = 0; r < 4; r++) {
        int hh = h_lo + ((r >= 2) ? 8 : 0);
        int bb = bl0 + (r & 1);
        g_sum[(b0 + bb) * 1024 + h0 + hh] = (float)cnt[r];
    }
}

// ---------------- K4: readout ---------------------------------------------
__global__ void k_out(const float* __restrict__ W3, const float* __restrict__ b3,
                      float* __restrict__ out)
{
    __shared__ float s0[128], s1[128];
    int b = blockIdx.x, t = threadIdx.x;
    float a0 = 0.f, a1 = 0.f;
    for (int hh = t; hh < 1024; hh += 128) {
        float s = g_sum[b * 1024 + hh];
        a0 += s * W3[hh];
        a1 += s * W3[1024 + hh];
    }
    s0[t] = a0; s1[t] = a1;
    __syncthreads();
    for (int o = 64; o > 0; o >>= 1) {
        if (t < o) { s0[t] += s0[t + o]; s1[t] += s1[t + o]; }
        __syncthreads();
    }
    if (t == 0) {
        out[b * 2 + 0] = s0[0] + b3[0];
        out[b * 2 + 1] = s1[0] + b3[1];
    }
}

// ---------------- launch ----------------------------------------------------
extern "C" void kernel_launch(void* const* d_in, const int* in_sizes, int n_in,
                              void* d_out, int out_size)
{
    const int*   inputs = (const int*)d_in[0];
    const float* emb    = (const float*)d_in[1];
    const float* W1     = (const float*)d_in[2];
    const float* b1     = (const float*)d_in[3];
    const float* W2     = (const float*)d_in[4];
    const float* b2     = (const float*)d_in[5];
    const float* Wr2    = (const float*)d_in[6];
    const float* br2    = (const float*)d_in[7];
    const float* W3     = (const float*)d_in[8];
    const float* b3     = (const float*)d_in[9];
    float* out = (float*)d_out;

    cudaFuncSetAttribute(k_embed_l1, cudaFuncAttributeMaxDynamicSharedMemorySize, 131072);
    cudaFuncSetAttribute(k_gemm_I,  cudaFuncAttributeMaxDynamicSharedMemorySize, 66560);
    cudaFuncSetAttribute(k_scan,    cudaFuncAttributeMaxDynamicSharedMemorySize, 134400);

    k_quant<<<(H_ * H_ + 255) / 256, 256>>>(W2, Wr2);
    k_embed_l1<<<2048, 256, 130816>>>(inputs, emb, W1, b1);
    k_gemm_I<<<dim3(8, 1024), 256, 65792>>>();
    k_scan<<<128, 256, 134400>>>(b2, br2);
    k_out<<<128, 128>>>(W3, b3, out);
}

// round 5
// speedup vs baseline: 1.4497x; 1.0475x over previous
#include <cuda_runtime.h>
#include <cstdint>

#define B_    128
#define S_    1024
#define EMB_  100
#define EDIM_ 256
#define H_    1024

// Scratch (device globals: allocation-free rule)
__device__ float       g_I[S_ * B_ * H_];      // [s*128+b][h]  512 MB
__device__ signed char g_Xq[S_ * B_ * EDIM_];  // quantized layer-1 acts *16
__device__ signed char g_W2q[H_ * EDIM_];      // round(W2*16)
__device__ signed char g_Wrq[H_ * H_];         // round(Wr2*16)
__device__ float       g_sum[B_ * H_];         // spike counts

__device__ __forceinline__ uint32_t smem_u32(const void* p) {
    uint32_t a;
    asm("{ .reg .u64 t; cvta.to.shared.u64 t, %1; cvt.u32.u64 %0, t; }" : "=r"(a) : "l"(p));
    return a;
}

// ---------------- K0: weight quantization --------------------------------
__global__ void k_quant(const float* __restrict__ W2, const float* __restrict__ Wr2) {
    int i = blockIdx.x * blockDim.x + threadIdx.x;
    if (i < H_ * EDIM_) {
        float v = rintf(W2[i] * 16.f);
        v = fminf(fmaxf(v, -15.f), 15.f);
        g_W2q[i] = (signed char)v;
    }
    if (i < H_ * H_) {
        float v = rintf(Wr2[i] * 16.f);
        v = fminf(fmaxf(v, -15.f), 15.f);
        g_Wrq[i] = (signed char)v;
    }
}

// ---------------- K1: embedding + layer1 + quant_act ----------------------
__global__ __launch_bounds__(256) void k_embed_l1(
    const int* __restrict__ inputs, const float* __restrict__ emb,
    const float* __restrict__ W1, const float* __restrict__ b1)
{
    extern __shared__ char sm[];
    float* w1t = (float*)sm;               // [100][257]
    float* xs  = (float*)(sm + 102912);    // [64][104]
    float* b1s = (float*)(sm + 129536);
    int*   tok = (int*)(sm + 130560);

    int t = threadIdx.x;
    for (int idx = t; idx < EDIM_ * EMB_; idx += 256) {
        int h = idx / EMB_;
        int e = idx - h * EMB_;
        w1t[e * 257 + h] = W1[idx];
    }
    b1s[t] = b1[t];
    int r0 = blockIdx.x * 64;
    if (t < 64) {
        int R = r0 + t;
        tok[t] = inputs[(R & 127) * S_ + (R >> 7)];
    }
    __syncthreads();
    for (int idx = t; idx < 64 * 104; idx += 256) {
        int r = idx / 104;
        int e = idx - r * 104;
        xs[idx] = (e < EMB_) ? emb[tok[r] * EMB_ + e] : 0.f;
    }
    __syncthreads();

    int h = t;
    for (int rb = 0; rb < 8; rb++) {
        float acc[8];
#pragma unroll
        for (int i = 0; i < 8; i++) acc[i] = 0.f;
        for (int ec = 0; ec < 25; ec++) {
            float w0 = w1t[(4 * ec + 0) * 257 + h];
            float w1v = w1t[(4 * ec + 1) * 257 + h];
            float w2v = w1t[(4 * ec + 2) * 257 + h];
            float w3v = w1t[(4 * ec + 3) * 257 + h];
#pragma unroll
            for (int r8 = 0; r8 < 8; r8++) {
                const float4 x4 = *(const float4*)(xs + (rb * 8 + r8) * 104 + 4 * ec);
                acc[r8] += x4.x * w0 + x4.y * w1v + x4.z * w2v + x4.w * w3v;
            }
        }
#pragma unroll
        for (int r8 = 0; r8 < 8; r8++) {
            int R = r0 + rb * 8 + r8;
            float v = acc[r8] + b1s[h];
            v = fmaxf(v, 0.f);
            float q = fminf(rintf(v * 16.f), 15.f);
            g_Xq[R * EDIM_ + h] = (signed char)q;
        }
    }
}

// ---------------- K2: I = Xq @ W2q^T / 256 (dp4a GEMM) ---------------------
__global__ __launch_bounds__(256, 2) void k_gemm_I() {
    extern __shared__ char sm[];
    int* xsm = (int*)sm;              // [128][64]
    int* wsm = (int*)(sm + 32768);    // [64][129]
    int t = threadIdx.x;
    int rt0 = blockIdx.y * 128;
    int ht0 = blockIdx.x * 128;
    const int* Xw = (const int*)g_Xq;
    const int* Ww = (const int*)g_W2q;
    for (int idx = t; idx < 8192; idx += 256) {
        int r = idx >> 6, kc = idx & 63;
        xsm[r * 64 + kc] = Xw[(rt0 + r) * 64 + kc];
        wsm[kc * 129 + r] = Ww[(ht0 + r) * 64 + kc];
    }
    __syncthreads();
    int tx = t & 15, ty = t >> 4;
    int acc[8][8];
#pragma unroll
    for (int i = 0; i < 8; i++)
#pragma unroll
        for (int j = 0; j < 8; j++) acc[i][j] = 0;

    for (int kc = 0; kc < 64; kc++) {
        int a[8], b[8];
#pragma unroll
        for (int i = 0; i < 8; i++) a[i] = xsm[(ty * 8 + i) * 64 + kc];
#pragma unroll
        for (int j = 0; j < 8; j++) b[j] = wsm[kc * 129 + tx + 16 * j];
#pragma unroll
        for (int i = 0; i < 8; i++)
#pragma unroll
            for (int j = 0; j < 8; j++) acc[i][j] = __dp4a(a[i], b[j], acc[i][j]);
    }
#pragma unroll
    for (int i = 0; i < 8; i++)
#pragma unroll
        for (int j = 0; j < 8; j++)
            g_I[(size_t)(rt0 + ty * 8 + i) * 1024 + ht0 + tx + 16 * j] =
                (float)acc[i][j] * (1.f / 256.f);
}

// ---------------- K3: recurrent LIF scan (v4: A-fragments in registers) -----
// 16 clusters x 8 CTAs x 256 threads. CTA = 128 h-rows x 8 batches.
// Warp w owns h rows [16w, 16w+16). Weight A-fragments are ldmatrix'd ONCE at
// init into 128 registers/thread; the step loop is pure {LDS pk word -> 8 ALU
// -> mma.sync.m16n8k32.s8} x32 with no shared-memory weight traffic.
// Spike exchange: packed bits, double-buffered, remote st.shared::cluster +
// cluster.sync. Next-step g_I prefetch overlaps the cluster barrier.
__global__ void __cluster_dims__(8, 1, 1) __launch_bounds__(256, 1)
k_scan(const float* __restrict__ b2, const float* __restrict__ br2)
{
    extern __shared__ char sm[];
    // [0, 131072)        W slab (init-only), 128 rows x 1024 B, 16B-unit XOR swizzle
    // [131072, 133376)   pk[2][8][36] packed spike words (row stride 36)
    // [133376, 134400)   sb[8][128] spike byte staging
    unsigned*      pk = (unsigned*)(sm + 131072);
    unsigned char* sb = (unsigned char*)(sm + 133376);

    int t  = threadIdx.x;
    int cr = blockIdx.x & 7;            // cluster rank
    int b0 = (blockIdx.x >> 3) * 8;     // global batch base
    int h0 = cr * 128;                  // global h base

    uint32_t smb  = smem_u32(sm);
    uint32_t pk_a = smb + 131072;

    // ---- init: swizzled weight slab + zero pk ----
    const int4* Wr4 = (const int4*)g_Wrq;
    int4* wS4 = (int4*)sm;
    for (int idx = t; idx < 8192; idx += 256) {
        int hh = idx >> 6, u = idx & 63;
        wS4[hh * 64 + (u ^ (hh & 7))] = Wr4[(h0 + hh) * 64 + u];
    }
    for (int i = t; i < 576; i += 256) pk[i] = 0u;
    __syncthreads();

    int lane = t & 31, w = t >> 5;
    int qd = lane >> 2;                 // l/4: C row, B batch
    int qm = lane & 3;                  // l%4
    int h_lo = 16 * w + qd;             // C rows: h_lo, h_lo+8
    int bl0  = qm * 2;                  // C cols: bl0, bl0+1

    // ldmatrix source lane mapping (init only)
    int mm  = lane >> 3, r8 = lane & 7;
    int lrow = 16 * w + ((mm & 1) << 3) + r8;
    int uhi  = mm >> 1;
    uint32_t arow = smb + (uint32_t)lrow * 1024u;
    int sbit = qm * 4;

    // ---- load all A-fragments into registers (once) ----
    unsigned aR[32][4];
#pragma unroll
    for (int kc = 0; kc < 32; kc++) {
        uint32_t addr = arow + (uint32_t)(((kc * 2 + uhi) ^ r8) << 4);
        asm volatile(
            "ldmatrix.sync.aligned.m8n8.x4.shared.b16 {%0,%1,%2,%3}, [%4];"
            : "=r"(aR[kc][0]), "=r"(aR[kc][1]), "=r"(aR[kc][2]), "=r"(aR[kc][3])
            : "r"(addr));
    }

    asm volatile("barrier.cluster.arrive.aligned;" ::: "memory");
    asm volatile("barrier.cluster.wait.aligned;" ::: "memory");

    float b2lo = b2[h0 + h_lo], b2hi = b2[h0 + h_lo + 8];
    float brlo = br2[h0 + h_lo], brhi = br2[h0 + h_lo + 8];

    float mem[4] = {0.f, 0.f, 0.f, 0.f};
    float spf[4] = {0.f, 0.f, 0.f, 0.f};
    int   cnt[4] = {0, 0, 0, 0};

    const float* Ib = g_I + (size_t)b0 * 1024 + h0;
    // prefetch step-0 feed-forward currents
    float Iv0 = Ib[(size_t)(bl0    ) * 1024 + h_lo];
    float Iv1 = Ib[(size_t)(bl0 + 1) * 1024 + h_lo];
    float Iv2 = Ib[(size_t)(bl0    ) * 1024 + h_lo + 8];
    float Iv3 = Ib[(size_t)(bl0 + 1) * 1024 + h_lo + 8];

    for (int s = 0; s < 1024; s++) {
        int q = s & 1, qn = q ^ 1;

        int c[16];
#pragma unroll
        for (int i = 0; i < 16; i++) c[i] = 0;

        const unsigned* pkq = pk + q * 288 + qd * 36;
#pragma unroll
        for (int kc = 0; kc < 32; kc++) {
            unsigned wbits = pkq[kc];
            unsigned u0 = (wbits >> sbit) & 0xFu;
            unsigned u1 = (wbits >> (sbit + 16)) & 0xFu;
            unsigned bb0 = (u0 * 0x204081u) & 0x01010101u;
            unsigned bb1 = (u1 * 0x204081u) & 0x01010101u;
            int* cc = c + (kc & 3) * 4;
            asm volatile(
                "mma.sync.aligned.m16n8k32.row.col.s32.s8.s8.s32 "
                "{%0,%1,%2,%3}, {%4,%5,%6,%7}, {%8,%9}, {%0,%1,%2,%3};"
                : "+r"(cc[0]), "+r"(cc[1]), "+r"(cc[2]), "+r"(cc[3])
                : "r"(aR[kc][0]), "r"(aR[kc][1]), "r"(aR[kc][2]), "r"(aR[kc][3]),
                  "r"(bb0), "r"(bb1));
        }
        int accs[4];
        accs[0] = (c[0] + c[4]) + (c[8]  + c[12]);
        accs[1] = (c[1] + c[5]) + (c[9]  + c[13]);
        accs[2] = (c[2] + c[6]) + (c[10] + c[14]);
        accs[3] = (c[3] + c[7]) + (c[11] + c[15]);

        // membrane update (exact replication of reference op order)
        float Ivs[4] = {Iv0, Iv1, Iv2, Iv3};
#pragma unroll
        for (int r = 0; r < 4; r++) {
            float R = (float)accs[r] * 0.0625f;               // exact
            float m = __fmul_rn(mem[r], 0.2f);
            if (spf[r] != 0.f) m = 0.f;                       // *(1-spike)
            m = __fadd_rn(m, Ivs[r]);
            m = __fadd_rn(m, (r >= 2) ? b2hi : b2lo);
            m = __fadd_rn(m, R);
            m = __fadd_rn(m, (r >= 2) ? brhi : brlo);
            mem[r] = m;
            bool sk = m > 0.5f;
            spf[r] = sk ? 1.f : 0.f;
            cnt[r] += sk ? 1 : 0;
            int hh = h_lo + ((r >= 2) ? 8 : 0);
            int bb = bl0 + (r & 1);
            sb[bb * 128 + hh] = sk ? 1u : 0u;
        }
        __syncthreads();

        // pack: warp w packs batch w (4 words of 32 h-bits), broadcast to 8 ranks
        unsigned bal0 = __ballot_sync(0xffffffffu, sb[w * 128 +  0 + lane] != 0);
        unsigned bal1 = __ballot_sync(0xffffffffu, sb[w * 128 + 32 + lane] != 0);
        unsigned bal2 = __ballot_sync(0xffffffffu, sb[w * 128 + 64 + lane] != 0);
        unsigned bal3 = __ballot_sync(0xffffffffu, sb[w * 128 + 96 + lane] != 0);
        {
            int rank = lane >> 2;
            int wi   = lane & 3;
            unsigned word = (wi == 0) ? bal0 : (wi == 1) ? bal1
                          : (wi == 2) ? bal2 : bal3;
            uint32_t dst = pk_a + (uint32_t)(qn * 288 + w * 36 + cr * 4 + wi) * 4u;
            asm volatile(
                "{\n\t.reg .b32 ra;\n\t"
                "mapa.shared::cluster.u32 ra, %0, %1;\n\t"
                "st.shared::cluster.b32 [ra], %2;\n\t}"
                :: "r"(dst), "r"(rank), "r"(word) : "memory");
        }

        // prefetch next step's feed-forward currents (overlaps barrier wait)
        if (s < 1023) Ib += 131072;
        Iv0 = Ib[(size_t)(bl0    ) * 1024 + h_lo];
        Iv1 = Ib[(size_t)(bl0 + 1) * 1024 + h_lo];
        Iv2 = Ib[(size_t)(bl0    ) * 1024 + h_lo + 8];
        Iv3 = Ib[(size_t)(bl0 + 1) * 1024 + h_lo + 8];

        asm volatile("barrier.cluster.arrive.aligned;" ::: "memory");
        asm volatile("barrier.cluster.wait.aligned;" ::: "memory");
    }

#pragma unroll
    for (int r = 0; r < 4; r++) {
        int hh = h_lo + ((r >= 2) ? 8 : 0);
        int bb = bl0 + (r & 1);
        g_sum[(b0 + bb) * 1024 + h0 + hh] = (float)cnt[r];
    }
}

// ---------------- K4: readout ---------------------------------------------
__global__ void k_out(const float* __restrict__ W3, const float* __restrict__ b3,
                      float* __restrict__ out)
{
    __shared__ float s0[128], s1[128];
    int b = blockIdx.x, t = threadIdx.x;
    float a0 = 0.f, a1 = 0.f;
    for (int hh = t; hh < 1024; hh += 128) {
        float s = g_sum[b * 1024 + hh];
        a0 += s * W3[hh];
        a1 += s * W3[1024 + hh];
    }
    s0[t] = a0; s1[t] = a1;
    __syncthreads();
    for (int o = 64; o > 0; o >>= 1) {
        if (t < o) { s0[t] += s0[t + o]; s1[t] += s1[t + o]; }
        __syncthreads();
    }
    if (t == 0) {
        out[b * 2 + 0] = s0[0] + b3[0];
        out[b * 2 + 1] = s1[0] + b3[1];
    }
}

// ---------------- launch ----------------------------------------------------
extern "C" void kernel_launch(void* const* d_in, const int* in_sizes, int n_in,
                              void* d_out, int out_size)
{
    const int*   inputs = (const int*)d_in[0];
    const float* emb    = (const float*)d_in[1];
    const float* W1     = (const float*)d_in[2];
    const float* b1     = (const float*)d_in[3];
    const float* W2     = (const float*)d_in[4];
    const float* b2     = (const float*)d_in[5];
    const float* Wr2    = (const float*)d_in[6];
    const float* br2    = (const float*)d_in[7];
    const float* W3     = (const float*)d_in[8];
    const float* b3     = (const float*)d_in[9];
    float* out = (float*)d_out;

    cudaFuncSetAttribute(k_embed_l1, cudaFuncAttributeMaxDynamicSharedMemorySize, 131072);
    cudaFuncSetAttribute(k_gemm_I,  cudaFuncAttributeMaxDynamicSharedMemorySize, 66560);
    cudaFuncSetAttribute(k_scan,    cudaFuncAttributeMaxDynamicSharedMemorySize, 134400);

    k_quant<<<(H_ * H_ + 255) / 256, 256>>>(W2, Wr2);
    k_embed_l1<<<2048, 256, 130816>>>(inputs, emb, W1, b1);
    k_gemm_I<<<dim3(8, 1024), 256, 65792>>>();
    k_scan<<<128, 256, 134400>>>(b2, br2);
    k_out<<<128, 128>>>(W3, b3, out);
}